// round 14
// baseline (speedup 1.0000x reference)
#include <cuda_runtime.h>

#define T_DIM 512
#define B_DIM 256
#define D_DIM 128
#define H_DIM 128
#define Q_DIM 8

// sigmoid / tanh via fast exp (MUFU.EX2-based, ~2^-21 rel err; safe at +-inf)
__device__ __forceinline__ float fsig(float x) {
    return __fdividef(1.f, 1.f + __expf(-x));
}
__device__ __forceinline__ float ftanh(float x) {
    return 1.f - __fdividef(2.f, __expf(2.f * x) + 1.f);
}

// One CTA per batch element, 128 threads, whole T=512 recurrence in-block.
// z = Wx.x_t + Wh.h_t + b. The x-half (zx) is computed ONE STEP AHEAD from
// register-resident x (LDG'd a step earlier), so the per-step critical path
// is only the h-half: 8 LDS.128 + 32 FFMA. W lives in registers.
__global__ __launch_bounds__(128) void qlstm_scan_kernel(
    const float* __restrict__ x,     // (T,B,D)
    const float* __restrict__ Wf, const float* __restrict__ bf,
    const float* __restrict__ thf, const float* __restrict__ Uf, const float* __restrict__ cf,
    const float* __restrict__ Wi, const float* __restrict__ bi,
    const float* __restrict__ thi, const float* __restrict__ Ui, const float* __restrict__ ci,
    const float* __restrict__ Wg, const float* __restrict__ bg,
    const float* __restrict__ thg, const float* __restrict__ Ug, const float* __restrict__ cg,
    const float* __restrict__ Wo, const float* __restrict__ bo,
    const float* __restrict__ tho, const float* __restrict__ Uo, const float* __restrict__ co,
    float* __restrict__ out)         // outs (T,B,H) ++ hx (B,H) ++ cx (B,H)
{
    __shared__ float comb[128];          // h_t only
    __shared__ float zbuf[32];           // z + bias for the 32 outputs
    __shared__ float4 cbuf4[4 * 8];      // per-warp cos tables (4 warps x 32 floats)

    const int tid  = threadIdx.x;
    const int b    = blockIdx.x;
    const int lane = tid & 31;
    const int wid  = tid >> 5;
    const int o    = tid >> 2;       // 0..31: this thread's z-output (g*8+q)
    const int part = tid & 3;        // quarter of each 128-dot
    const int g_o  = o >> 3;
    const int q_o  = o & 7;

    // ---- W into registers (invariant) ----
    // row layout: [0:128)=x weights, [128:256)=h weights (comb was [x,h]).
    // Thread (o,part) owns float4 indices {4j+part} of each half (j=0..7).
    float4 Wx[8], Wh[8];
    {
        const float* wsrc = (o < 16) ? ((o < 8) ? Wf : Wi) : ((o < 24) ? Wg : Wo);
        const float4* wrow = (const float4*)(wsrc + (o & 7) * 256);
#pragma unroll
        for (int j = 0; j < 8; ++j) {
            Wx[j] = wrow[4 * j + part];
            Wh[j] = wrow[32 + 4 * j + part];
        }
    }

    const float bias_reg = ((g_o == 0) ? bf : (g_o == 1) ? bi : (g_o == 2) ? bg : bo)[q_o];
    const int gl = lane >> 3;
    const float th_reg = ((gl == 0) ? thf : (gl == 1) ? thi : (gl == 2) ? thg : tho)[lane & 7];

    // U in registers: thread t permanently owns hidden index hh = tid
    float Ur[4][8];
    float cbr[4];
    {
        const float* Us[4] = {Uf, Ui, Ug, Uo};
        const float* cs[4] = {cf, ci, cg, co};
#pragma unroll
        for (int g = 0; g < 4; ++g) {
            const float4 u0 = ((const float4*)(Us[g] + tid * 8))[0];
            const float4 u1 = ((const float4*)(Us[g] + tid * 8))[1];
            Ur[g][0] = u0.x; Ur[g][1] = u0.y; Ur[g][2] = u0.z; Ur[g][3] = u0.w;
            Ur[g][4] = u1.x; Ur[g][5] = u1.y; Ur[g][6] = u1.z; Ur[g][7] = u1.w;
            cbr[g] = cs[g][tid];
        }
    }

    // ---- x pipeline: xv holds x_{t+1} quads; zxpart holds this thread's
    //      x-dot partial for step t (ready before the step starts).
    const int X_STRIDE4 = B_DIM * D_DIM / 4;            // float4 stride per step
    const float4* xp4 = (const float4*)(x + (size_t)b * D_DIM) + part;  // x_0
    float4 xv[8];
#pragma unroll
    for (int j = 0; j < 8; ++j) xv[j] = xp4[4 * j];     // x_0
    float zxpart = 0.f;
#pragma unroll
    for (int j = 0; j < 8; ++j)
        zxpart += xv[j].x * Wx[j].x + xv[j].y * Wx[j].y
                + xv[j].z * Wx[j].z + xv[j].w * Wx[j].w;  // zx for step 0
    xp4 += X_STRIDE4;
#pragma unroll
    for (int j = 0; j < 8; ++j) xv[j] = xp4[4 * j];     // x_1
    xp4 += X_STRIDE4;                                   // -> x_2

    comb[tid] = 0.f;                                    // h_0
    float creg  = 0.f;
    float*      optr = out + b * H_DIM + tid;
    float hlast = 0.f;
    __syncthreads();

    const unsigned FULL = 0xffffffffu;
    float* mycbuf = (float*)(cbuf4 + wid * 8);

    for (int step = 0; step < T_DIM; ++step) {
        // ---- critical path: h-half of the dot (8 LDS.128 + 32 FFMA) ----
        const float4* c4 = (const float4*)comb;
        float ax = zxpart, ay = 0.f, az = 0.f, aw = 0.f;
#pragma unroll
        for (int j = 0; j < 8; ++j) {
            const float4 cv = c4[4 * j + part];
            ax += cv.x * Wh[j].x; ay += cv.y * Wh[j].y;
            az += cv.z * Wh[j].z; aw += cv.w * Wh[j].w;
        }
        float z = (ax + ay) + (az + aw);
        z += __shfl_xor_sync(FULL, z, 1);
        z += __shfl_xor_sync(FULL, z, 2);
        if (part == 0) zbuf[o] = z + bias_reg;

        // ---- latency filler: zx for step t+1 from xv, then prefetch x_{t+2}
        float zxn = 0.f;
#pragma unroll
        for (int j = 0; j < 8; ++j)
            zxn += xv[j].x * Wx[j].x + xv[j].y * Wx[j].y
                 + xv[j].z * Wx[j].z + xv[j].w * Wx[j].w;
        zxpart = zxn;
        if (step + 2 < T_DIM) {
#pragma unroll
            for (int j = 0; j < 8; ++j) xv[j] = xp4[4 * j];
            xp4 += X_STRIDE4;
        }
        __syncthreads();  // zbuf published; all comb reads done

        // ---- qgate: per-warp cos table, then per-thread prefix products ----
        const float cc = __cosf(zbuf[lane] + th_reg);
        mycbuf[lane] = cc;
        __syncwarp();

        // ---- U projection: a_g = cb_g + sum_q e[g,q]*U[g][hh][q] ----
        float acc[4];
#pragma unroll
        for (int g = 0; g < 4; ++g) {
            const float4 cA = cbuf4[wid * 8 + g * 2];
            const float4 cB = cbuf4[wid * 8 + g * 2 + 1];
            const float s67 = cB.z * cB.w;
            const float s47 = cB.x * cB.y * s67;
            const float e0  = cA.y * cA.z * cA.w * s47;   // c1..c7
            const float cp1 = cA.x * cA.y;
            const float cp2 = cp1 * cA.z;
            const float cp3 = cp2 * cA.w;
            const float cp4 = cp3 * cB.x;
            const float cp5 = cp4 * cB.y;
            const float cp6 = cp5 * cB.z;
            const float cp7 = cp6 * cB.w;
            float a = cbr[g];
            a += e0  * Ur[g][0];
            a += cp1 * Ur[g][1];
            a += cp2 * Ur[g][2];
            a += cp3 * Ur[g][3];
            a += cp4 * Ur[g][4];
            a += cp5 * Ur[g][5];
            a += cp6 * Ur[g][6];
            a += cp7 * Ur[g][7];
            acc[g] = a;
        }

        // ---- cell update ----
        const float fv = fsig(acc[0]);
        const float iv = fsig(acc[1]);
        const float gv = ftanh(acc[2]);
        const float ov = fsig(acc[3]);
        creg = fv * creg + iv * gv;
        const float hv = ov * ftanh(creg);

        comb[tid] = hv;
        *optr = hv;
        optr += B_DIM * H_DIM;
        hlast = hv;
        __syncthreads();  // h published for next step
    }

    // finals: hx then cx
    const size_t base = (size_t)T_DIM * B_DIM * H_DIM;
    out[base + b * H_DIM + tid] = hlast;
    out[base + (size_t)B_DIM * H_DIM + b * H_DIM + tid] = creg;
}

extern "C" void kernel_launch(void* const* d_in, const int* in_sizes, int n_in,
                              void* d_out, int out_size) {
    (void)in_sizes; (void)n_in; (void)out_size;
    const float* x   = (const float*)d_in[0];
    const float* Wf  = (const float*)d_in[1];
    const float* bf  = (const float*)d_in[2];
    const float* thf = (const float*)d_in[3];
    const float* Uf  = (const float*)d_in[4];
    const float* cf  = (const float*)d_in[5];
    const float* Wi  = (const float*)d_in[6];
    const float* bi  = (const float*)d_in[7];
    const float* thi = (const float*)d_in[8];
    const float* Ui  = (const float*)d_in[9];
    const float* ci  = (const float*)d_in[10];
    const float* Wg  = (const float*)d_in[11];
    const float* bg  = (const float*)d_in[12];
    const float* thg = (const float*)d_in[13];
    const float* Ug  = (const float*)d_in[14];
    const float* cg  = (const float*)d_in[15];
    const float* Wo  = (const float*)d_in[16];
    const float* bo  = (const float*)d_in[17];
    const float* tho = (const float*)d_in[18];
    const float* Uo  = (const float*)d_in[19];
    const float* co  = (const float*)d_in[20];
    float* out = (float*)d_out;

    qlstm_scan_kernel<<<B_DIM, 128>>>(
        x,
        Wf, bf, thf, Uf, cf,
        Wi, bi, thi, Ui, ci,
        Wg, bg, thg, Ug, cg,
        Wo, bo, tho, Uo, co,
        out);
}

// round 15
// speedup vs baseline: 1.6210x; 1.6210x over previous
#include <cuda_runtime.h>

#define T_DIM 512
#define B_DIM 256
#define D_DIM 128
#define H_DIM 128
#define Q_DIM 8

// MUFU.TANH-based activations (sm_75+): ~2^-11 abs err, one MUFU each.
__device__ __forceinline__ float tanh_approx(float x) {
    float r;
    asm("tanh.approx.f32 %0, %1;" : "=f"(r) : "f"(x));
    return r;
}
__device__ __forceinline__ float fsig(float x) {          // sigmoid
    return fmaf(tanh_approx(0.5f * x), 0.5f, 0.5f);
}

// One CTA per batch element. 128 threads. Whole T=512 recurrence in-block.
// W in registers (16 float4/thread). The z-owning thread (part==0) computes
// cos(z + bias + theta) BEFORE the barrier and publishes the cos table
// directly; consumers read it with broadcast LDS.128 -- the per-warp cos
// stage (LDS zbuf + cos + STS + syncwarp + LDS) is gone from the chain.
__global__ __launch_bounds__(128) void qlstm_scan_kernel(
    const float* __restrict__ x,     // (T,B,D)
    const float* __restrict__ Wf, const float* __restrict__ bf,
    const float* __restrict__ thf, const float* __restrict__ Uf, const float* __restrict__ cf,
    const float* __restrict__ Wi, const float* __restrict__ bi,
    const float* __restrict__ thi, const float* __restrict__ Ui, const float* __restrict__ ci,
    const float* __restrict__ Wg, const float* __restrict__ bg,
    const float* __restrict__ thg, const float* __restrict__ Ug, const float* __restrict__ cg,
    const float* __restrict__ Wo, const float* __restrict__ bo,
    const float* __restrict__ tho, const float* __restrict__ Uo, const float* __restrict__ co,
    float* __restrict__ out)         // outs (T,B,H) ++ hx (B,H) ++ cx (B,H)
{
    __shared__ float comb[256];      // [0:128)=x_t, [128:256)=h_t
    __shared__ float4 ct4[8];        // CTA-wide cos table: cos(z+b+th) for 32 outputs

    const int tid  = threadIdx.x;
    const int b    = blockIdx.x;
    const int o    = tid >> 2;       // 0..31: this thread's z-output (g*8+q)
    const int part = tid & 3;        // quarter of the 256-dot
    const int g_o  = o >> 3;
    const int q_o  = o & 7;

    // ---- W into registers (invariant across all 512 steps) ----
    float4 Wreg[16];
    {
        const float* wsrc = (o < 16) ? ((o < 8) ? Wf : Wi) : ((o < 24) ? Wg : Wo);
        const float4* wrow = (const float4*)(wsrc + (o & 7) * 256);
#pragma unroll
        for (int j = 0; j < 16; ++j)
            Wreg[j] = wrow[4 * j + part];
    }

    // bias + theta pre-combined for my z-output (both constant per o)
    const float bias_th =
        ((g_o == 0) ? bf : (g_o == 1) ? bi : (g_o == 2) ? bg : bo)[q_o] +
        ((g_o == 0) ? thf : (g_o == 1) ? thi : (g_o == 2) ? thg : tho)[q_o];

    // U in registers: thread t permanently owns hidden index hh = tid
    float Ur[4][8];
    float cbr[4];
    {
        const float* Us[4] = {Uf, Ui, Ug, Uo};
        const float* cs[4] = {cf, ci, cg, co};
#pragma unroll
        for (int g = 0; g < 4; ++g) {
            const float4 u0 = ((const float4*)(Us[g] + tid * 8))[0];
            const float4 u1 = ((const float4*)(Us[g] + tid * 8))[1];
            Ur[g][0] = u0.x; Ur[g][1] = u0.y; Ur[g][2] = u0.z; Ur[g][3] = u0.w;
            Ur[g][4] = u1.x; Ur[g][5] = u1.y; Ur[g][6] = u1.z; Ur[g][7] = u1.w;
            cbr[g] = cs[g][tid];
        }
    }

    // initial state + running pointers
    comb[tid]       = x[b * D_DIM + tid];   // x_0
    comb[128 + tid] = 0.f;                  // h_0
    float creg  = 0.f;
    float xcur  = x[(size_t)B_DIM * D_DIM + b * D_DIM + tid];        // x_1 prefetched
    const float* xptr = x + (size_t)2 * B_DIM * D_DIM + b * D_DIM + tid;  // -> x_2
    float*       optr = out + b * H_DIM + tid;
    float hlast = 0.f;
    __syncthreads();

    const unsigned FULL = 0xffffffffu;
    float* ctable = (float*)ct4;

    for (int step = 0; step < T_DIM; ++step) {
        // ---- z[o] = comb . W[o]  (4 threads per output) ----
        const float4* c4 = (const float4*)comb;
        float ax = 0.f, ay = 0.f, az = 0.f, aw = 0.f;
#pragma unroll
        for (int j = 0; j < 16; ++j) {
            const float4 cv = c4[4 * j + part];
            ax += cv.x * Wreg[j].x; ay += cv.y * Wreg[j].y;
            az += cv.z * Wreg[j].z; aw += cv.w * Wreg[j].w;
        }
        float z = (ax + ay) + (az + aw);
        z += __shfl_xor_sync(FULL, z, 1);
        z += __shfl_xor_sync(FULL, z, 2);
        // owning thread finishes the qgate cos BEFORE the barrier
        if (part == 0) ctable[o] = __cosf(z + bias_th);
        __syncthreads();  // ctable published; all comb reads done

        // stage x_{t+1} into comb (dead region post-sync) + prefetch x_{t+2}
        comb[tid] = xcur;
        if (step + 2 < T_DIM) {
            xcur = *xptr;
            xptr += B_DIM * D_DIM;
        }

        // ---- per-thread prefix/suffix products from broadcast cos table ----
        // e[g,0] = c1*...*c7 ; e[g,q>=1] = c0*...*cq
        float acc[4];
#pragma unroll
        for (int g = 0; g < 4; ++g) {
            const float4 cA = ct4[g * 2];
            const float4 cB = ct4[g * 2 + 1];
            const float s67 = cB.z * cB.w;
            const float s47 = cB.x * cB.y * s67;
            const float e0  = cA.y * cA.z * cA.w * s47;   // c1..c7
            const float cp1 = cA.x * cA.y;
            const float cp2 = cp1 * cA.z;
            const float cp3 = cp2 * cA.w;
            const float cp4 = cp3 * cB.x;
            const float cp5 = cp4 * cB.y;
            const float cp6 = cp5 * cB.z;
            const float cp7 = cp6 * cB.w;
            float a = cbr[g];
            a += e0  * Ur[g][0];
            a += cp1 * Ur[g][1];
            a += cp2 * Ur[g][2];
            a += cp3 * Ur[g][3];
            a += cp4 * Ur[g][4];
            a += cp5 * Ur[g][5];
            a += cp6 * Ur[g][6];
            a += cp7 * Ur[g][7];
            acc[g] = a;
        }

        // ---- cell update (MUFU.TANH-based activations) ----
        const float fv = fsig(acc[0]);
        const float iv = fsig(acc[1]);
        const float gv = tanh_approx(acc[2]);
        const float ov = fsig(acc[3]);
        creg = fv * creg + iv * gv;
        const float hv = ov * tanh_approx(creg);

        comb[128 + tid] = hv;
        *optr = hv;
        optr += B_DIM * H_DIM;
        hlast = hv;
        __syncthreads();  // h (and staged x) published for next step
    }

    // finals: hx then cx
    const size_t base = (size_t)T_DIM * B_DIM * H_DIM;
    out[base + b * H_DIM + tid] = hlast;
    out[base + (size_t)B_DIM * H_DIM + b * H_DIM + tid] = creg;
}

extern "C" void kernel_launch(void* const* d_in, const int* in_sizes, int n_in,
                              void* d_out, int out_size) {
    (void)in_sizes; (void)n_in; (void)out_size;
    const float* x   = (const float*)d_in[0];
    const float* Wf  = (const float*)d_in[1];
    const float* bf  = (const float*)d_in[2];
    const float* thf = (const float*)d_in[3];
    const float* Uf  = (const float*)d_in[4];
    const float* cf  = (const float*)d_in[5];
    const float* Wi  = (const float*)d_in[6];
    const float* bi  = (const float*)d_in[7];
    const float* thi = (const float*)d_in[8];
    const float* Ui  = (const float*)d_in[9];
    const float* ci  = (const float*)d_in[10];
    const float* Wg  = (const float*)d_in[11];
    const float* bg  = (const float*)d_in[12];
    const float* thg = (const float*)d_in[13];
    const float* Ug  = (const float*)d_in[14];
    const float* cg  = (const float*)d_in[15];
    const float* Wo  = (const float*)d_in[16];
    const float* bo  = (const float*)d_in[17];
    const float* tho = (const float*)d_in[18];
    const float* Uo  = (const float*)d_in[19];
    const float* co  = (const float*)d_in[20];
    float* out = (float*)d_out;

    qlstm_scan_kernel<<<B_DIM, 128>>>(
        x,
        Wf, bf, thf, Uf, cf,
        Wi, bi, thi, Ui, ci,
        Wg, bg, thg, Ug, cg,
        Wo, bo, tho, Uo, co,
        out);
}